// round 1
// baseline (speedup 1.0000x reference)
#include <cuda_runtime.h>

#define NN 100000
#define EE 1600000

// ---------------- scratch (static __device__, no allocation) ----------------
__device__ float g_xw[NN * 40];      // per-layer xw (concat heads)
__device__ float g_lin[NN * 40];     // skip linear output
__device__ float g_agg[NN * 40];     // gat aggregate (layers 1,2)
__device__ float g_h[NN * 40];       // current hidden state
__device__ float g_asrc[NN * 8];     // per-head src scores (padded to 8)
__device__ float g_adst[NN * 8];
__device__ float g_denom[NN * 8];    // softmax denominators
__device__ float g_aggs[NN * 240];   // layer-3 per-head aggregated h2 [N,6,40]
__device__ float g_vsrc[240];        // W3[:,h,:]@as3[h]  -> [6,40]
__device__ float g_vdst[240];
__device__ float g_wm[280 * 128];    // fused final weight [280,128pad]
__device__ float g_biasc[128];       // b3 + lb3

__device__ __forceinline__ float lrelu(float v) { return v > 0.f ? v : 0.2f * v; }
__device__ __forceinline__ float elu1(float v) { return v > 0.f ? v : (__expf(v) - 1.f); }

// ---------------- node GEMM: xw = x@W, lin = x@lw+lb, scores, self denom ----
// block = 128 threads handles 32 nodes; 32 | NN so no row guard.
template <int KDIM>
__global__ __launch_bounds__(128) void node_gemm_k(
    const float* __restrict__ x, const float* __restrict__ W,
    const float* __restrict__ lw, const float* __restrict__ lb,
    const float* __restrict__ as_, const float* __restrict__ ad_) {
  __shared__ float sW[KDIM * 80];
  __shared__ float sX[32 * (KDIM + 1)];
  __shared__ float sAs[40], sAd[40], sLb[40];
  const int t = threadIdx.x;
  for (int i = t; i < KDIM * 80; i += 128) {
    int k = i / 80, j = i % 80;
    sW[i] = (j < 40) ? W[k * 40 + j] : lw[k * 40 + (j - 40)];
  }
  const int nb = blockIdx.x * 32;
  for (int i = t; i < 32 * KDIM; i += 128) {
    int r = i / KDIM, k = i % KDIM;
    sX[r * (KDIM + 1) + k] = x[(nb + r) * KDIM + k];
  }
  if (t < 40) { sAs[t] = as_[t]; sAd[t] = ad_[t]; sLb[t] = lb[t]; }
  __syncthreads();

  const int row = t >> 2, cg = t & 3, c0 = cg * 20;
  float acc[20];
#pragma unroll
  for (int j = 0; j < 20; j++) acc[j] = 0.f;
#pragma unroll 5
  for (int k = 0; k < KDIM; k++) {
    float a = sX[row * (KDIM + 1) + k];
    const float4* w4 = reinterpret_cast<const float4*>(&sW[k * 80 + c0]);
#pragma unroll
    for (int q = 0; q < 5; q++) {
      float4 w = w4[q];
      acc[4 * q + 0] += a * w.x;
      acc[4 * q + 1] += a * w.y;
      acc[4 * q + 2] += a * w.z;
      acc[4 * q + 3] += a * w.w;
    }
  }
  const int n = nb + row;
  if (cg < 2) {
    float4* o = reinterpret_cast<float4*>(&g_xw[n * 40 + c0]);
#pragma unroll
    for (int q = 0; q < 5; q++)
      o[q] = make_float4(acc[4 * q], acc[4 * q + 1], acc[4 * q + 2], acc[4 * q + 3]);
    float s0 = 0.f, s1 = 0.f, d0 = 0.f, d1 = 0.f;
#pragma unroll
    for (int j = 0; j < 10; j++) {
      s0 += acc[j] * sAs[c0 + j];       d0 += acc[j] * sAd[c0 + j];
      s1 += acc[10 + j] * sAs[c0 + 10 + j]; d1 += acc[10 + j] * sAd[c0 + 10 + j];
    }
    const int h0 = 2 * cg;
    g_asrc[n * 8 + h0] = s0;      g_asrc[n * 8 + h0 + 1] = s1;
    g_adst[n * 8 + h0] = d0;      g_adst[n * 8 + h0 + 1] = d1;
    g_denom[n * 8 + h0] = __expf(lrelu(s0 + d0));      // self-loop term
    g_denom[n * 8 + h0 + 1] = __expf(lrelu(s1 + d1));
  } else {
    const int lc = c0 - 40;
    float4* o = reinterpret_cast<float4*>(&g_lin[n * 40 + lc]);
#pragma unroll
    for (int q = 0; q < 5; q++)
      o[q] = make_float4(acc[4 * q] + sLb[lc + 4 * q], acc[4 * q + 1] + sLb[lc + 4 * q + 1],
                         acc[4 * q + 2] + sLb[lc + 4 * q + 2], acc[4 * q + 3] + sLb[lc + 4 * q + 3]);
  }
}

// ---------------- layers 1/2 edge passes (4 heads) ----------------
__global__ __launch_bounds__(256) void edge_denom_l12(const int* __restrict__ ei) {
  int e = blockIdx.x * 256 + threadIdx.x;
  if (e >= EE) return;
  int s = ei[e], d = ei[EE + e];
  float4 sa = *reinterpret_cast<const float4*>(&g_asrc[s * 8]);
  float4 da = *reinterpret_cast<const float4*>(&g_adst[d * 8]);
  float4 w = make_float4(__expf(lrelu(sa.x + da.x)), __expf(lrelu(sa.y + da.y)),
                         __expf(lrelu(sa.z + da.z)), __expf(lrelu(sa.w + da.w)));
  atomicAdd(reinterpret_cast<float4*>(&g_denom[d * 8]), w);
}

__global__ __launch_bounds__(256) void self_agg_l12() {
  int n = blockIdx.x * 256 + threadIdx.x;
  if (n >= NN) return;
  float4 sa = *reinterpret_cast<const float4*>(&g_asrc[n * 8]);
  float4 da = *reinterpret_cast<const float4*>(&g_adst[n * 8]);
  float4 dn = *reinterpret_cast<const float4*>(&g_denom[n * 8]);
  float al[4] = {__expf(lrelu(sa.x + da.x)) / dn.x, __expf(lrelu(sa.y + da.y)) / dn.y,
                 __expf(lrelu(sa.z + da.z)) / dn.z, __expf(lrelu(sa.w + da.w)) / dn.w};
#pragma unroll
  for (int j = 0; j < 10; j++) {
    float4 v = *reinterpret_cast<const float4*>(&g_xw[n * 40 + 4 * j]);
    v.x *= al[(4 * j + 0) / 10];
    v.y *= al[(4 * j + 1) / 10];
    v.z *= al[(4 * j + 2) / 10];
    v.w *= al[(4 * j + 3) / 10];
    *reinterpret_cast<float4*>(&g_agg[n * 40 + 4 * j]) = v;
  }
}

__global__ __launch_bounds__(256) void edge_agg_l12(const int* __restrict__ ei) {
  int e = blockIdx.x * 256 + threadIdx.x;
  if (e >= EE) return;
  int s = ei[e], d = ei[EE + e];
  float4 sa = *reinterpret_cast<const float4*>(&g_asrc[s * 8]);
  float4 da = *reinterpret_cast<const float4*>(&g_adst[d * 8]);
  float4 dn = *reinterpret_cast<const float4*>(&g_denom[d * 8]);
  float al[4] = {__expf(lrelu(sa.x + da.x)) / dn.x, __expf(lrelu(sa.y + da.y)) / dn.y,
                 __expf(lrelu(sa.z + da.z)) / dn.z, __expf(lrelu(sa.w + da.w)) / dn.w};
#pragma unroll
  for (int j = 0; j < 10; j++) {
    float4 v = __ldg(reinterpret_cast<const float4*>(&g_xw[s * 40 + 4 * j]));
    v.x *= al[(4 * j + 0) / 10];
    v.y *= al[(4 * j + 1) / 10];
    v.z *= al[(4 * j + 2) / 10];
    v.w *= al[(4 * j + 3) / 10];
    atomicAdd(reinterpret_cast<float4*>(&g_agg[d * 40 + 4 * j]), v);
  }
}

// ---------------- h = elu(agg + lin + bias) ----------------
__global__ __launch_bounds__(256) void combine_elu(const float* __restrict__ b) {
  int i = blockIdx.x * 256 + threadIdx.x;
  if (i >= NN * 10) return;
  float4 a = reinterpret_cast<const float4*>(g_agg)[i];
  float4 l = reinterpret_cast<const float4*>(g_lin)[i];
  int c = (i * 4) % 40;
  float4 r;
  r.x = elu1(a.x + l.x + b[c + 0]);
  r.y = elu1(a.y + l.y + b[c + 1]);
  r.z = elu1(a.z + l.z + b[c + 2]);
  r.w = elu1(a.w + l.w + b[c + 3]);
  reinterpret_cast<float4*>(g_h)[i] = r;
}

// ---------------- layer 3 prep ----------------
__global__ void l3_prep_v(const float* __restrict__ W3, const float* __restrict__ as3,
                          const float* __restrict__ ad3) {
  int t = threadIdx.x;
  if (t >= 240) return;
  int h = t / 40, k = t % 40;
  float s = 0.f, d = 0.f;
  for (int c = 0; c < 121; c++) {
    float w = W3[k * 726 + h * 121 + c];
    s += w * as3[h * 121 + c];
    d += w * ad3[h * 121 + c];
  }
  g_vsrc[t] = s;
  g_vdst[t] = d;
}

__global__ void l3_prep_w(const float* __restrict__ W3, const float* __restrict__ lw3,
                          const float* __restrict__ b3, const float* __restrict__ lb3) {
  int i = blockIdx.x * 256 + threadIdx.x;
  if (i < 280 * 128) {
    int r = i / 128, c = i % 128;
    float v = 0.f;
    if (c < 121)
      v = (r < 240) ? W3[(r % 40) * 726 + (r / 40) * 121 + c] * (1.f / 6.f)
                    : lw3[(r - 240) * 121 + c];
    g_wm[i] = v;
  }
  if (i < 128) g_biasc[i] = (i < 121) ? b3[i] + lb3[i] : 0.f;
}

__global__ __launch_bounds__(256) void l3_scores() {
  __shared__ float sVs[240], sVd[240];
  int t = threadIdx.x;
  if (t < 240) { sVs[t] = g_vsrc[t]; sVd[t] = g_vdst[t]; }
  __syncthreads();
  int n = blockIdx.x * 256 + t;
  if (n >= NN) return;
  float xr[40];
  const float4* hp = reinterpret_cast<const float4*>(&g_h[n * 40]);
#pragma unroll
  for (int j = 0; j < 10; j++) {
    float4 v = hp[j];
    xr[4 * j] = v.x; xr[4 * j + 1] = v.y; xr[4 * j + 2] = v.z; xr[4 * j + 3] = v.w;
  }
#pragma unroll
  for (int h = 0; h < 6; h++) {
    float s = 0.f, d = 0.f;
#pragma unroll
    for (int k = 0; k < 40; k++) { s += xr[k] * sVs[h * 40 + k]; d += xr[k] * sVd[h * 40 + k]; }
    g_asrc[n * 8 + h] = s;
    g_adst[n * 8 + h] = d;
    g_denom[n * 8 + h] = __expf(lrelu(s + d));  // self loop
  }
}

__global__ __launch_bounds__(256) void edge_denom_l3(const int* __restrict__ ei) {
  int e = blockIdx.x * 256 + threadIdx.x;
  if (e >= EE) return;
  int s = ei[e], d = ei[EE + e];
  float4 sa = *reinterpret_cast<const float4*>(&g_asrc[s * 8]);
  float2 sb = *reinterpret_cast<const float2*>(&g_asrc[s * 8 + 4]);
  float4 da = *reinterpret_cast<const float4*>(&g_adst[d * 8]);
  float2 db = *reinterpret_cast<const float2*>(&g_adst[d * 8 + 4]);
  float4 w = make_float4(__expf(lrelu(sa.x + da.x)), __expf(lrelu(sa.y + da.y)),
                         __expf(lrelu(sa.z + da.z)), __expf(lrelu(sa.w + da.w)));
  float2 w2 = make_float2(__expf(lrelu(sb.x + db.x)), __expf(lrelu(sb.y + db.y)));
  atomicAdd(reinterpret_cast<float4*>(&g_denom[d * 8]), w);
  atomicAdd(reinterpret_cast<float2*>(&g_denom[d * 8 + 4]), w2);
}

__global__ __launch_bounds__(256) void self_agg_l3() {
  int n = blockIdx.x * 256 + threadIdx.x;
  if (n >= NN) return;
  float al[6];
#pragma unroll
  for (int h = 0; h < 6; h++)
    al[h] = __expf(lrelu(g_asrc[n * 8 + h] + g_adst[n * 8 + h])) / g_denom[n * 8 + h];
  const float4* hp = reinterpret_cast<const float4*>(&g_h[n * 40]);
  float4 xr[10];
#pragma unroll
  for (int j = 0; j < 10; j++) xr[j] = hp[j];
#pragma unroll
  for (int h = 0; h < 6; h++) {
    float a = al[h];
    float4* o = reinterpret_cast<float4*>(&g_aggs[n * 240 + h * 40]);
#pragma unroll
    for (int j = 0; j < 10; j++)
      o[j] = make_float4(xr[j].x * a, xr[j].y * a, xr[j].z * a, xr[j].w * a);
  }
}

__global__ __launch_bounds__(256) void edge_agg_l3(const int* __restrict__ ei) {
  int e = blockIdx.x * 256 + threadIdx.x;
  if (e >= EE) return;
  int s = ei[e], d = ei[EE + e];
  float al[6];
#pragma unroll
  for (int h = 0; h < 6; h++)
    al[h] = __expf(lrelu(g_asrc[s * 8 + h] + g_adst[d * 8 + h])) / g_denom[d * 8 + h];
#pragma unroll
  for (int j = 0; j < 10; j++) {
    float4 v = __ldg(reinterpret_cast<const float4*>(&g_h[s * 40 + 4 * j]));
#pragma unroll
    for (int h = 0; h < 6; h++) {
      atomicAdd(reinterpret_cast<float4*>(&g_aggs[d * 240 + h * 40 + 4 * j]),
                make_float4(v.x * al[h], v.y * al[h], v.z * al[h], v.w * al[h]));
    }
  }
}

// ---------------- final fused GEMM: out = [aggs | h] @ Wm + biasc ----------------
__global__ __launch_bounds__(256, 2) void final_gemm(float* __restrict__ out) {
  __shared__ float sA[20][128];
  __shared__ float sB[20][128];
  const int t = threadIdx.x;
  const int bm = blockIdx.x * 128;
  const int ty = t >> 4, tx = t & 15;
  float acc[8][8];
#pragma unroll
  for (int i = 0; i < 8; i++)
#pragma unroll
    for (int j = 0; j < 8; j++) acc[i][j] = 0.f;

  for (int kt = 0; kt < 280; kt += 20) {
#pragma unroll
    for (int i = 0; i < 10; i++) {
      int idx = i * 256 + t;
      int m = idx / 20, kk = idx % 20;
      int row = bm + m, k = kt + kk;
      float v = 0.f;
      if (row < NN) v = (k < 240) ? g_aggs[row * 240 + k] : g_h[row * 40 + (k - 240)];
      sA[kk][m] = v;
    }
#pragma unroll
    for (int i = 0; i < 10; i++) {
      int idx = i * 256 + t;
      int kk = idx / 128, c = idx % 128;
      sB[kk][c] = g_wm[(kt + kk) * 128 + c];
    }
    __syncthreads();
#pragma unroll
    for (int kk = 0; kk < 20; kk++) {
      float a[8], b[8];
#pragma unroll
      for (int i = 0; i < 8; i++) a[i] = sA[kk][ty * 8 + i];
#pragma unroll
      for (int j = 0; j < 8; j++) b[j] = sB[kk][tx * 8 + j];
#pragma unroll
      for (int i = 0; i < 8; i++)
#pragma unroll
        for (int j = 0; j < 8; j++) acc[i][j] += a[i] * b[j];
    }
    __syncthreads();
  }
#pragma unroll
  for (int i = 0; i < 8; i++) {
    int row = bm + ty * 8 + i;
    if (row >= NN) continue;
#pragma unroll
    for (int j = 0; j < 8; j++) {
      int c = tx * 8 + j;
      if (c < 121) out[row * 121 + c] = acc[i][j] + g_biasc[c];
    }
  }
}

// ---------------- launch ----------------
extern "C" void kernel_launch(void* const* d_in, const int* in_sizes, int n_in,
                              void* d_out, int out_size) {
  const float* x   = (const float*)d_in[0];
  const int*   ei  = (const int*)d_in[1];
  const float* W1  = (const float*)d_in[2];
  const float* as1 = (const float*)d_in[3];
  const float* ad1 = (const float*)d_in[4];
  const float* b1  = (const float*)d_in[5];
  const float* lw1 = (const float*)d_in[6];
  const float* lb1 = (const float*)d_in[7];
  const float* W2  = (const float*)d_in[8];
  const float* as2 = (const float*)d_in[9];
  const float* ad2 = (const float*)d_in[10];
  const float* b2  = (const float*)d_in[11];
  const float* lw2 = (const float*)d_in[12];
  const float* lb2 = (const float*)d_in[13];
  const float* W3  = (const float*)d_in[14];
  const float* as3 = (const float*)d_in[15];
  const float* ad3 = (const float*)d_in[16];
  const float* b3  = (const float*)d_in[17];
  const float* lw3 = (const float*)d_in[18];
  const float* lb3 = (const float*)d_in[19];
  float* out = (float*)d_out;

  float* hbuf = nullptr;
  cudaGetSymbolAddress((void**)&hbuf, g_h);

  const int EB = EE / 256;            // 6250 exact
  const int NB = (NN + 255) / 256;    // 391
  const int CB = (NN * 10 + 255) / 256;

  // layer 1
  node_gemm_k<50><<<NN / 32, 128>>>(x, W1, lw1, lb1, as1, ad1);
  edge_denom_l12<<<EB, 256>>>(ei);
  self_agg_l12<<<NB, 256>>>();
  edge_agg_l12<<<EB, 256>>>(ei);
  combine_elu<<<CB, 256>>>(b1);
  // layer 2
  node_gemm_k<40><<<NN / 32, 128>>>(hbuf, W2, lw2, lb2, as2, ad2);
  edge_denom_l12<<<EB, 256>>>(ei);
  self_agg_l12<<<NB, 256>>>();
  edge_agg_l12<<<EB, 256>>>(ei);
  combine_elu<<<CB, 256>>>(b2);
  // layer 3
  l3_prep_v<<<1, 256>>>(W3, as3, ad3);
  l3_prep_w<<<140, 256>>>(W3, lw3, b3, lb3);
  l3_scores<<<NB, 256>>>();
  edge_denom_l3<<<EB, 256>>>(ei);
  self_agg_l3<<<NB, 256>>>();
  edge_agg_l3<<<EB, 256>>>(ei);
  final_gemm<<<(NN + 127) / 128, 256>>>(out);
}

// round 4
// speedup vs baseline: 2.0672x; 2.0672x over previous
#include <cuda_runtime.h>

#define NN 100000
#define EE 1600000

typedef unsigned long long u64;

// ---------------- scratch (static __device__, no allocation) ----------------
__device__ float g_xw[NN * 40];      // per-layer xw (concat heads)
__device__ float g_lin[NN * 40];     // skip linear output (incl lb)
__device__ float g_h[NN * 40];       // current hidden state
__device__ float g_asrc[NN * 8];     // per-head src scores (padded to 8)
__device__ float g_adst[NN * 8];
__device__ float g_aggs[NN * 240];   // layer-3 per-head aggregated h2 [N,6,40]
__device__ float g_vsrc[240];        // W3[:,h,:]@as3[h]  -> [6,40]
__device__ float g_vdst[240];
__device__ float g_wm[280 * 128];    // fused final weight [280,128pad]
__device__ float g_biasc[128];       // b3 + lb3

// CSR scratch
__device__ int g_deg[NN];
__device__ int g_incl[NN];
__device__ int g_bsum[256];
__device__ int g_boff[256];
__device__ int g_rowstart[NN + 1];
__device__ int g_cursor[NN];
__device__ int g_csr_src[EE];

__device__ __forceinline__ float lrelu(float v) { return v > 0.f ? v : 0.2f * v; }
__device__ __forceinline__ float elu1(float v) { return v > 0.f ? v : (__expf(v) - 1.f); }

// ================= CSR build =================
__global__ void zero_deg() {
  int i = blockIdx.x * 256 + threadIdx.x;
  if (i < NN) g_deg[i] = 0;
}
__global__ void hist_k(const int* __restrict__ ei) {
  int e = blockIdx.x * 256 + threadIdx.x;
  if (e < EE) atomicAdd(&g_deg[ei[EE + e]], 1);
}
__global__ void scan1_k() {  // 196 blocks x 512
  __shared__ int sb[512];
  int t = threadIdx.x;
  int i = blockIdx.x * 512 + t;
  int v = (i < NN) ? g_deg[i] : 0;
  sb[t] = v;
  __syncthreads();
  for (int off = 1; off < 512; off <<= 1) {
    int x = (t >= off) ? sb[t - off] : 0;
    __syncthreads();
    sb[t] += x;
    __syncthreads();
  }
  if (i < NN) g_incl[i] = sb[t];
  if (t == 511) g_bsum[blockIdx.x] = sb[511];
}
__global__ void scan2_k(int nb) {  // 1 block, 256 threads
  __shared__ int sb[256];
  int t = threadIdx.x;
  int own = (t < nb) ? g_bsum[t] : 0;
  sb[t] = own;
  __syncthreads();
  for (int off = 1; off < 256; off <<= 1) {
    int x = (t >= off) ? sb[t - off] : 0;
    __syncthreads();
    sb[t] += x;
    __syncthreads();
  }
  g_boff[t] = sb[t] - own;  // exclusive
}
__global__ void scan3_k() {
  int i = blockIdx.x * 256 + threadIdx.x;
  if (i < NN) {
    int rs = g_incl[i] - g_deg[i] + g_boff[i / 512];
    g_rowstart[i] = rs;
    g_cursor[i] = rs;
    if (i == NN - 1) g_rowstart[NN] = EE;
  }
}
__global__ void scatter_k(const int* __restrict__ ei) {
  int e = blockIdx.x * 256 + threadIdx.x;
  if (e < EE) {
    int s = ei[e], d = ei[EE + e];
    int p = atomicAdd(&g_cursor[d], 1);
    g_csr_src[p] = s;
  }
}

// ---------------- node GEMM: xw = x@W, lin = x@lw+lb, scores ----
template <int KDIM>
__global__ __launch_bounds__(128) void node_gemm_k(
    const float* __restrict__ x, const float* __restrict__ W,
    const float* __restrict__ lw, const float* __restrict__ lb,
    const float* __restrict__ as_, const float* __restrict__ ad_) {
  __shared__ float sW[KDIM * 80];
  __shared__ float sX[32 * (KDIM + 1)];
  __shared__ float sAs[40], sAd[40], sLb[40];
  const int t = threadIdx.x;
  for (int i = t; i < KDIM * 80; i += 128) {
    int k = i / 80, j = i % 80;
    sW[i] = (j < 40) ? W[k * 40 + j] : lw[k * 40 + (j - 40)];
  }
  const int nb = blockIdx.x * 32;
  for (int i = t; i < 32 * KDIM; i += 128) {
    int r = i / KDIM, k = i % KDIM;
    sX[r * (KDIM + 1) + k] = x[(nb + r) * KDIM + k];
  }
  if (t < 40) { sAs[t] = as_[t]; sAd[t] = ad_[t]; sLb[t] = lb[t]; }
  __syncthreads();

  const int row = t >> 2, cg = t & 3, c0 = cg * 20;
  float acc[20];
#pragma unroll
  for (int j = 0; j < 20; j++) acc[j] = 0.f;
#pragma unroll 5
  for (int k = 0; k < KDIM; k++) {
    float a = sX[row * (KDIM + 1) + k];
    const float4* w4 = reinterpret_cast<const float4*>(&sW[k * 80 + c0]);
#pragma unroll
    for (int q = 0; q < 5; q++) {
      float4 w = w4[q];
      acc[4 * q + 0] += a * w.x;
      acc[4 * q + 1] += a * w.y;
      acc[4 * q + 2] += a * w.z;
      acc[4 * q + 3] += a * w.w;
    }
  }
  const int n = nb + row;
  if (cg < 2) {
    float4* o = reinterpret_cast<float4*>(&g_xw[n * 40 + c0]);
#pragma unroll
    for (int q = 0; q < 5; q++)
      o[q] = make_float4(acc[4 * q], acc[4 * q + 1], acc[4 * q + 2], acc[4 * q + 3]);
    float s0 = 0.f, s1 = 0.f, d0 = 0.f, d1 = 0.f;
#pragma unroll
    for (int j = 0; j < 10; j++) {
      s0 += acc[j] * sAs[c0 + j];           d0 += acc[j] * sAd[c0 + j];
      s1 += acc[10 + j] * sAs[c0 + 10 + j]; d1 += acc[10 + j] * sAd[c0 + 10 + j];
    }
    const int h0 = 2 * cg;
    g_asrc[n * 8 + h0] = s0;      g_asrc[n * 8 + h0 + 1] = s1;
    g_adst[n * 8 + h0] = d0;      g_adst[n * 8 + h0 + 1] = d1;
  } else {
    const int lc = c0 - 40;
    float4* o = reinterpret_cast<float4*>(&g_lin[n * 40 + lc]);
#pragma unroll
    for (int q = 0; q < 5; q++)
      o[q] = make_float4(acc[4 * q] + sLb[lc + 4 * q], acc[4 * q + 1] + sLb[lc + 4 * q + 1],
                         acc[4 * q + 2] + sLb[lc + 4 * q + 2], acc[4 * q + 3] + sLb[lc + 4 * q + 3]);
  }
}

// ================= fused CSR aggregation, layers 1/2 (4 heads) =================
// 10-lane groups, 3 per warp (lanes 30,31 idle). Lane gt owns comps 4gt..4gt+3.
// Lanes gt<4 compute per-head exp weights; broadcast via shfl inside group.
__global__ __launch_bounds__(320) void csr_agg_l12(const float* __restrict__ bias) {
  const int t = threadIdx.x;
  const int lane = t & 31, warp = t >> 5;
  const int g = lane / 10;
  const int gt = lane - 10 * g;
  if (g == 3) return;
  const int dst = blockIdx.x * 30 + warp * 3 + g;
  if (dst >= NN) return;
  const unsigned mask = 0x3FFu << (10 * g);
  const int base = 10 * g;

  const int ha = (4 * gt) / 10;
  const int hb = (4 * gt + 3) / 10;
  const int m = 10 * (ha + 1) - 4 * gt;  // comps j>=m belong to head hb

  const float ad = (gt < 4) ? g_adst[dst * 8 + gt] : 0.f;
  float den = 0.f;
  float4 acc = make_float4(0.f, 0.f, 0.f, 0.f);

  const int row0 = g_rowstart[dst], row1 = g_rowstart[dst + 1];
  int sCur = dst;  // self-loop first
  for (int e = row0 - 1; e < row1; e++) {
    int sNxt = (e + 1 < row1) ? g_csr_src[e + 1] : 0;
    float w = 0.f;
    if (gt < 4) {
      w = __expf(lrelu(g_asrc[sCur * 8 + gt] + ad));
      den += w;
    }
    float wA = __shfl_sync(mask, w, base + ha);
    float wB = __shfl_sync(mask, w, base + hb);
    float4 v = *reinterpret_cast<const float4*>(&g_xw[sCur * 40 + 4 * gt]);
    acc.x += ((0 >= m) ? wB : wA) * v.x;
    acc.y += ((1 >= m) ? wB : wA) * v.y;
    acc.z += ((2 >= m) ? wB : wA) * v.z;
    acc.w += ((3 >= m) ? wB : wA) * v.w;
    sCur = sNxt;
  }
  float dA = __shfl_sync(mask, den, base + ha);
  float dB = __shfl_sync(mask, den, base + hb);

  float4 l = *reinterpret_cast<const float4*>(&g_lin[dst * 40 + 4 * gt]);
  float b0 = bias[4 * gt + 0], b1 = bias[4 * gt + 1];
  float b2 = bias[4 * gt + 2], b3 = bias[4 * gt + 3];
  float4 o;
  o.x = elu1(acc.x / ((0 >= m) ? dB : dA) + l.x + b0);
  o.y = elu1(acc.y / ((1 >= m) ? dB : dA) + l.y + b1);
  o.z = elu1(acc.z / ((2 >= m) ? dB : dA) + l.z + b2);
  o.w = elu1(acc.w / ((3 >= m) ? dB : dA) + l.w + b3);
  *reinterpret_cast<float4*>(&g_h[dst * 40 + 4 * gt]) = o;
}

// ================= fused CSR aggregation, layer 3 (6 heads) =================
// Lane gt owns float4 slice gt of h; accumulates it for all 6 heads.
__global__ __launch_bounds__(320) void csr_agg_l3() {
  const int t = threadIdx.x;
  const int lane = t & 31, warp = t >> 5;
  const int g = lane / 10;
  const int gt = lane - 10 * g;
  if (g == 3) return;
  const int dst = blockIdx.x * 30 + warp * 3 + g;
  if (dst >= NN) return;
  const unsigned mask = 0x3FFu << (10 * g);
  const int base = 10 * g;

  const float ad = (gt < 6) ? g_adst[dst * 8 + gt] : 0.f;
  float den = 0.f;
  float4 acc[6];
#pragma unroll
  for (int h = 0; h < 6; h++) acc[h] = make_float4(0.f, 0.f, 0.f, 0.f);

  const int row0 = g_rowstart[dst], row1 = g_rowstart[dst + 1];
  int sCur = dst;  // self-loop first
  for (int e = row0 - 1; e < row1; e++) {
    int sNxt = (e + 1 < row1) ? g_csr_src[e + 1] : 0;
    float w = 0.f;
    if (gt < 6) {
      w = __expf(lrelu(g_asrc[sCur * 8 + gt] + ad));
      den += w;
    }
    float4 v = __ldg(reinterpret_cast<const float4*>(&g_h[sCur * 40 + 4 * gt]));
#pragma unroll
    for (int h = 0; h < 6; h++) {
      float wh = __shfl_sync(mask, w, base + h);
      acc[h].x += wh * v.x;
      acc[h].y += wh * v.y;
      acc[h].z += wh * v.z;
      acc[h].w += wh * v.w;
    }
    sCur = sNxt;
  }
#pragma unroll
  for (int h = 0; h < 6; h++) {
    float dh = __shfl_sync(mask, den, base + h);
    float inv = 1.f / dh;
    float4 o = make_float4(acc[h].x * inv, acc[h].y * inv, acc[h].z * inv, acc[h].w * inv);
    *reinterpret_cast<float4*>(&g_aggs[dst * 240 + h * 40 + 4 * gt]) = o;
  }
}

// ---------------- layer 3 prep ----------------
__global__ void l3_prep_v(const float* __restrict__ W3, const float* __restrict__ as3,
                          const float* __restrict__ ad3) {
  int t = threadIdx.x;
  if (t >= 240) return;
  int h = t / 40, k = t % 40;
  float s = 0.f, d = 0.f;
  for (int c = 0; c < 121; c++) {
    float w = W3[k * 726 + h * 121 + c];
    s += w * as3[h * 121 + c];
    d += w * ad3[h * 121 + c];
  }
  g_vsrc[t] = s;
  g_vdst[t] = d;
}

__global__ void l3_prep_w(const float* __restrict__ W3, const float* __restrict__ lw3,
                          const float* __restrict__ b3, const float* __restrict__ lb3) {
  int i = blockIdx.x * 256 + threadIdx.x;
  if (i < 280 * 128) {
    int r = i / 128, c = i % 128;
    float v = 0.f;
    if (c < 121)
      v = (r < 240) ? W3[(r % 40) * 726 + (r / 40) * 121 + c] * (1.f / 6.f)
                    : lw3[(r - 240) * 121 + c];
    g_wm[i] = v;
  }
  if (i < 128) g_biasc[i] = (i < 121) ? b3[i] + lb3[i] : 0.f;
}

__global__ __launch_bounds__(256) void l3_scores() {
  __shared__ float sVs[240], sVd[240];
  int t = threadIdx.x;
  if (t < 240) { sVs[t] = g_vsrc[t]; sVd[t] = g_vdst[t]; }
  __syncthreads();
  int n = blockIdx.x * 256 + t;
  if (n >= NN) return;
  float xr[40];
  const float4* hp = reinterpret_cast<const float4*>(&g_h[n * 40]);
#pragma unroll
  for (int j = 0; j < 10; j++) {
    float4 v = hp[j];
    xr[4 * j] = v.x; xr[4 * j + 1] = v.y; xr[4 * j + 2] = v.z; xr[4 * j + 3] = v.w;
  }
#pragma unroll
  for (int h = 0; h < 6; h++) {
    float s = 0.f, d = 0.f;
#pragma unroll
    for (int k = 0; k < 40; k++) { s += xr[k] * sVs[h * 40 + k]; d += xr[k] * sVd[h * 40 + k]; }
    g_asrc[n * 8 + h] = s;
    g_adst[n * 8 + h] = d;
  }
}

// ---------------- final fused GEMM: out = [aggs | h] @ Wm + biasc, f32x2 ----------------
__global__ __launch_bounds__(256, 2) void final_gemm(float* __restrict__ out) {
  __shared__ __align__(16) float sA[20][128];
  __shared__ __align__(16) float sB[20][128];
  const int t = threadIdx.x;
  const int bm = blockIdx.x * 128;
  const int ty = t >> 4, tx = t & 15;
  u64 acc[8][4];
#pragma unroll
  for (int i = 0; i < 8; i++)
#pragma unroll
    for (int j = 0; j < 4; j++) acc[i][j] = 0ULL;

  for (int kt = 0; kt < 280; kt += 20) {
#pragma unroll
    for (int i = 0; i < 10; i++) {
      int idx = i * 256 + t;
      int mrow = idx / 20, kk = idx % 20;
      int row = bm + mrow, k = kt + kk;
      float v = 0.f;
      if (row < NN) v = (k < 240) ? g_aggs[row * 240 + k] : g_h[row * 40 + (k - 240)];
      sA[kk][mrow] = v;
    }
#pragma unroll
    for (int i = 0; i < 10; i++) {
      int idx = i * 256 + t;
      int kk = idx / 128, c = idx % 128;
      sB[kk][c] = g_wm[(kt + kk) * 128 + c];
    }
    __syncthreads();
#pragma unroll
    for (int kk = 0; kk < 20; kk++) {
      float a[8];
      u64 b[4];
#pragma unroll
      for (int i = 0; i < 8; i++) a[i] = sA[kk][ty * 8 + i];
      const u64* bp = reinterpret_cast<const u64*>(&sB[kk][tx * 8]);
#pragma unroll
      for (int j = 0; j < 4; j++) b[j] = bp[j];
#pragma unroll
      for (int i = 0; i < 8; i++) {
        u64 ap;
        asm("mov.b64 %0, {%1, %1};" : "=l"(ap) : "f"(a[i]));
#pragma unroll
        for (int j = 0; j < 4; j++)
          asm("fma.rn.f32x2 %0, %1, %2, %0;" : "+l"(acc[i][j]) : "l"(ap), "l"(b[j]));
      }
    }
    __syncthreads();
  }
#pragma unroll
  for (int i = 0; i < 8; i++) {
    int row = bm + ty * 8 + i;
    if (row >= NN) continue;
#pragma unroll
    for (int j = 0; j < 4; j++) {
      float lo, hi;
      asm("mov.b64 {%0, %1}, %2;" : "=f"(lo), "=f"(hi) : "l"(acc[i][j]));
      int c0 = tx * 8 + 2 * j;
      if (c0 < 121) out[row * 121 + c0] = lo + g_biasc[c0];
      if (c0 + 1 < 121) out[row * 121 + c0 + 1] = hi + g_biasc[c0 + 1];
    }
  }
}

// ---------------- launch ----------------
extern "C" void kernel_launch(void* const* d_in, const int* in_sizes, int n_in,
                              void* d_out, int out_size) {
  const float* x   = (const float*)d_in[0];
  const int*   ei  = (const int*)d_in[1];
  const float* W1  = (const float*)d_in[2];
  const float* as1 = (const float*)d_in[3];
  const float* ad1 = (const float*)d_in[4];
  const float* b1  = (const float*)d_in[5];
  const float* lw1 = (const float*)d_in[6];
  const float* lb1 = (const float*)d_in[7];
  const float* W2  = (const float*)d_in[8];
  const float* as2 = (const float*)d_in[9];
  const float* ad2 = (const float*)d_in[10];
  const float* b2  = (const float*)d_in[11];
  const float* lw2 = (const float*)d_in[12];
  const float* lb2 = (const float*)d_in[13];
  const float* W3  = (const float*)d_in[14];
  const float* as3 = (const float*)d_in[15];
  const float* ad3 = (const float*)d_in[16];
  const float* b3  = (const float*)d_in[17];
  const float* lw3 = (const float*)d_in[18];
  const float* lb3 = (const float*)d_in[19];
  float* out = (float*)d_out;

  float* hbuf = nullptr;
  cudaGetSymbolAddress((void**)&hbuf, g_h);

  const int EB = EE / 256;            // 6250 exact
  const int NB = (NN + 255) / 256;    // 391
  const int GB = (NN + 29) / 30;      // 3334 groups-of-30 blocks
  const int SB = (NN + 511) / 512;    // 196

  // CSR build (per launch; graph replays it deterministically)
  zero_deg<<<NB, 256>>>();
  hist_k<<<EB, 256>>>(ei);
  scan1_k<<<SB, 512>>>();
  scan2_k<<<1, 256>>>(SB);
  scan3_k<<<NB, 256>>>();
  scatter_k<<<EB, 256>>>(ei);

  // layer 1
  node_gemm_k<50><<<NN / 32, 128>>>(x, W1, lw1, lb1, as1, ad1);
  csr_agg_l12<<<GB, 320>>>(b1);
  // layer 2
  node_gemm_k<40><<<NN / 32, 128>>>(hbuf, W2, lw2, lb2, as2, ad2);
  csr_agg_l12<<<GB, 320>>>(b2);
  // layer 3
  l3_prep_v<<<1, 256>>>(W3, as3, ad3);
  l3_prep_w<<<140, 256>>>(W3, lw3, b3, lb3);
  l3_scores<<<NB, 256>>>();
  csr_agg_l3<<<GB, 320>>>();
  final_gemm<<<(NN + 127) / 128, 256>>>(out);
}

// round 5
// speedup vs baseline: 2.8018x; 1.3553x over previous
#include <cuda_runtime.h>

#define NN 100000
#define EE 1600000

typedef unsigned long long u64;

// ---------------- scratch (static __device__, no allocation) ----------------
__device__ float g_xw[NN * 40];      // per-layer xw (concat heads)
__device__ float g_lin[NN * 40];     // skip linear output (incl lb)
__device__ float g_h[NN * 40];       // current hidden state
__device__ float g_asrc[NN * 8];     // per-head src scores (padded to 8)
__device__ float g_adst[NN * 8];
__device__ float g_aggs[NN * 240];   // layer-3 per-head aggregated h2 [N,6,40]
__device__ float g_vsrc[240];        // W3[:,h,:]@as3[h]  -> [6,40]
__device__ float g_vdst[240];
__device__ float g_wm[280 * 128];    // fused final weight [280,128pad]
__device__ float g_biasc[128];       // b3 + lb3

// CSR scratch
__device__ int g_deg[NN];
__device__ int g_incl[NN];
__device__ int g_bsum[256];
__device__ int g_boff[256];
__device__ int g_rowstart[NN + 1];
__device__ int g_cursor[NN];
__device__ int g_csr_src[EE];

__device__ __forceinline__ float lrelu(float v) { return v > 0.f ? v : 0.2f * v; }
__device__ __forceinline__ float elu1(float v) { return v > 0.f ? v : (__expf(v) - 1.f); }

// ================= CSR build =================
__global__ void zero_deg() {
  int i = blockIdx.x * 256 + threadIdx.x;
  if (i < NN) g_deg[i] = 0;
}
__global__ void hist_k(const int* __restrict__ ei) {
  int e = blockIdx.x * 256 + threadIdx.x;
  if (e < EE) atomicAdd(&g_deg[ei[EE + e]], 1);
}
__global__ void scan1_k() {  // 196 blocks x 512
  __shared__ int sb[512];
  int t = threadIdx.x;
  int i = blockIdx.x * 512 + t;
  int v = (i < NN) ? g_deg[i] : 0;
  sb[t] = v;
  __syncthreads();
  for (int off = 1; off < 512; off <<= 1) {
    int x = (t >= off) ? sb[t - off] : 0;
    __syncthreads();
    sb[t] += x;
    __syncthreads();
  }
  if (i < NN) g_incl[i] = sb[t];
  if (t == 511) g_bsum[blockIdx.x] = sb[511];
}
__global__ void scan2_k(int nb) {  // 1 block, 256 threads
  __shared__ int sb[256];
  int t = threadIdx.x;
  int own = (t < nb) ? g_bsum[t] : 0;
  sb[t] = own;
  __syncthreads();
  for (int off = 1; off < 256; off <<= 1) {
    int x = (t >= off) ? sb[t - off] : 0;
    __syncthreads();
    sb[t] += x;
    __syncthreads();
  }
  g_boff[t] = sb[t] - own;  // exclusive
}
__global__ void scan3_k() {
  int i = blockIdx.x * 256 + threadIdx.x;
  if (i < NN) {
    int rs = g_incl[i] - g_deg[i] + g_boff[i / 512];
    g_rowstart[i] = rs;
    g_cursor[i] = rs;
    if (i == NN - 1) g_rowstart[NN] = EE;
  }
}
__global__ void scatter_k(const int* __restrict__ ei) {
  int e = blockIdx.x * 256 + threadIdx.x;
  if (e < EE) {
    int s = ei[e], d = ei[EE + e];
    int p = atomicAdd(&g_cursor[d], 1);
    g_csr_src[p] = s;
  }
}

// ---------------- node GEMM: xw = x@W, lin = x@lw+lb, scores ----
template <int KDIM>
__global__ __launch_bounds__(128) void node_gemm_k(
    const float* __restrict__ x, const float* __restrict__ W,
    const float* __restrict__ lw, const float* __restrict__ lb,
    const float* __restrict__ as_, const float* __restrict__ ad_) {
  __shared__ float sW[KDIM * 80];
  __shared__ float sX[32 * (KDIM + 1)];
  __shared__ float sAs[40], sAd[40], sLb[40];
  const int t = threadIdx.x;
  for (int i = t; i < KDIM * 80; i += 128) {
    int k = i / 80, j = i % 80;
    sW[i] = (j < 40) ? W[k * 40 + j] : lw[k * 40 + (j - 40)];
  }
  const int nb = blockIdx.x * 32;
  for (int i = t; i < 32 * KDIM; i += 128) {
    int r = i / KDIM, k = i % KDIM;
    sX[r * (KDIM + 1) + k] = x[(nb + r) * KDIM + k];
  }
  if (t < 40) { sAs[t] = as_[t]; sAd[t] = ad_[t]; sLb[t] = lb[t]; }
  __syncthreads();

  const int row = t >> 2, cg = t & 3, c0 = cg * 20;
  float acc[20];
#pragma unroll
  for (int j = 0; j < 20; j++) acc[j] = 0.f;
#pragma unroll 5
  for (int k = 0; k < KDIM; k++) {
    float a = sX[row * (KDIM + 1) + k];
    const float4* w4 = reinterpret_cast<const float4*>(&sW[k * 80 + c0]);
#pragma unroll
    for (int q = 0; q < 5; q++) {
      float4 w = w4[q];
      acc[4 * q + 0] += a * w.x;
      acc[4 * q + 1] += a * w.y;
      acc[4 * q + 2] += a * w.z;
      acc[4 * q + 3] += a * w.w;
    }
  }
  const int n = nb + row;
  if (cg < 2) {
    float4* o = reinterpret_cast<float4*>(&g_xw[n * 40 + c0]);
#pragma unroll
    for (int q = 0; q < 5; q++)
      o[q] = make_float4(acc[4 * q], acc[4 * q + 1], acc[4 * q + 2], acc[4 * q + 3]);
    float s0 = 0.f, s1 = 0.f, d0 = 0.f, d1 = 0.f;
#pragma unroll
    for (int j = 0; j < 10; j++) {
      s0 += acc[j] * sAs[c0 + j];           d0 += acc[j] * sAd[c0 + j];
      s1 += acc[10 + j] * sAs[c0 + 10 + j]; d1 += acc[10 + j] * sAd[c0 + 10 + j];
    }
    const int h0 = 2 * cg;
    g_asrc[n * 8 + h0] = s0;      g_asrc[n * 8 + h0 + 1] = s1;
    g_adst[n * 8 + h0] = d0;      g_adst[n * 8 + h0 + 1] = d1;
  } else {
    const int lc = c0 - 40;
    float4* o = reinterpret_cast<float4*>(&g_lin[n * 40 + lc]);
#pragma unroll
    for (int q = 0; q < 5; q++)
      o[q] = make_float4(acc[4 * q] + sLb[lc + 4 * q], acc[4 * q + 1] + sLb[lc + 4 * q + 1],
                         acc[4 * q + 2] + sLb[lc + 4 * q + 2], acc[4 * q + 3] + sLb[lc + 4 * q + 3]);
  }
}

// ================= fused CSR aggregation, layers 1/2 (4 heads) =================
// 10-lane groups, 3 per warp (lanes 30,31 idle). Lane gt owns comps 4gt..4gt+3.
// Software-pipelined: next edge's score + feature loaded before current compute.
__global__ __launch_bounds__(320) void csr_agg_l12(const float* __restrict__ bias) {
  const int t = threadIdx.x;
  const int lane = t & 31, warp = t >> 5;
  const int g = lane / 10;
  const int gt = lane - 10 * g;
  if (g == 3) return;
  const int dst = blockIdx.x * 30 + warp * 3 + g;
  if (dst >= NN) return;
  const unsigned mask = 0x3FFu << (10 * g);
  const int base = 10 * g;

  const int ha = (4 * gt) / 10;
  const int hb = (4 * gt + 3) / 10;
  const int m = 10 * (ha + 1) - 4 * gt;  // comps j>=m belong to head hb

  const float ad = (gt < 4) ? g_adst[dst * 8 + gt] : 0.f;
  float den = 0.f;
  float4 acc = make_float4(0.f, 0.f, 0.f, 0.f);

  const int row0 = g_rowstart[dst], row1 = g_rowstart[dst + 1];
  // pipeline: current = self-loop first
  float sc = (gt < 4) ? __ldg(&g_asrc[dst * 8 + gt]) : 0.f;
  float4 v = __ldg(reinterpret_cast<const float4*>(&g_xw[dst * 40 + 4 * gt]));
  for (int e = row0; ; e++) {
    const bool more = (e < row1);
    const int sNxt = more ? __ldg(&g_csr_src[e]) : 0;
    const float scN = (gt < 4) ? __ldg(&g_asrc[sNxt * 8 + gt]) : 0.f;
    const float4 vN = __ldg(reinterpret_cast<const float4*>(&g_xw[sNxt * 40 + 4 * gt]));
    float w = 0.f;
    if (gt < 4) {
      w = __expf(lrelu(sc + ad));
      den += w;
    }
    const float wA = __shfl_sync(mask, w, base + ha);
    const float wB = __shfl_sync(mask, w, base + hb);
    acc.x += ((0 >= m) ? wB : wA) * v.x;
    acc.y += ((1 >= m) ? wB : wA) * v.y;
    acc.z += ((2 >= m) ? wB : wA) * v.z;
    acc.w += ((3 >= m) ? wB : wA) * v.w;
    if (!more) break;
    sc = scN;
    v = vN;
  }
  float dA = __shfl_sync(mask, den, base + ha);
  float dB = __shfl_sync(mask, den, base + hb);

  float4 l = *reinterpret_cast<const float4*>(&g_lin[dst * 40 + 4 * gt]);
  float b0 = bias[4 * gt + 0], b1 = bias[4 * gt + 1];
  float b2 = bias[4 * gt + 2], b3 = bias[4 * gt + 3];
  float4 o;
  o.x = elu1(acc.x / ((0 >= m) ? dB : dA) + l.x + b0);
  o.y = elu1(acc.y / ((1 >= m) ? dB : dA) + l.y + b1);
  o.z = elu1(acc.z / ((2 >= m) ? dB : dA) + l.z + b2);
  o.w = elu1(acc.w / ((3 >= m) ? dB : dA) + l.w + b3);
  *reinterpret_cast<float4*>(&g_h[dst * 40 + 4 * gt]) = o;
}

// ================= fused CSR aggregation, layer 3 (6 heads) =================
// Lane gt owns float4 slice gt of h; accumulates it for all 6 heads. Pipelined.
__global__ __launch_bounds__(320) void csr_agg_l3() {
  const int t = threadIdx.x;
  const int lane = t & 31, warp = t >> 5;
  const int g = lane / 10;
  const int gt = lane - 10 * g;
  if (g == 3) return;
  const int dst = blockIdx.x * 30 + warp * 3 + g;
  if (dst >= NN) return;
  const unsigned mask = 0x3FFu << (10 * g);
  const int base = 10 * g;

  const float ad = (gt < 6) ? g_adst[dst * 8 + gt] : 0.f;
  float den = 0.f;
  float4 acc[6];
#pragma unroll
  for (int h = 0; h < 6; h++) acc[h] = make_float4(0.f, 0.f, 0.f, 0.f);

  const int row0 = g_rowstart[dst], row1 = g_rowstart[dst + 1];
  float sc = (gt < 6) ? __ldg(&g_asrc[dst * 8 + gt]) : 0.f;
  float4 v = __ldg(reinterpret_cast<const float4*>(&g_h[dst * 40 + 4 * gt]));
  for (int e = row0; ; e++) {
    const bool more = (e < row1);
    const int sNxt = more ? __ldg(&g_csr_src[e]) : 0;
    const float scN = (gt < 6) ? __ldg(&g_asrc[sNxt * 8 + gt]) : 0.f;
    const float4 vN = __ldg(reinterpret_cast<const float4*>(&g_h[sNxt * 40 + 4 * gt]));
    float w = 0.f;
    if (gt < 6) {
      w = __expf(lrelu(sc + ad));
      den += w;
    }
#pragma unroll
    for (int h = 0; h < 6; h++) {
      const float wh = __shfl_sync(mask, w, base + h);
      acc[h].x += wh * v.x;
      acc[h].y += wh * v.y;
      acc[h].z += wh * v.z;
      acc[h].w += wh * v.w;
    }
    if (!more) break;
    sc = scN;
    v = vN;
  }
#pragma unroll
  for (int h = 0; h < 6; h++) {
    float dh = __shfl_sync(mask, den, base + h);
    float inv = 1.f / dh;
    float4 o = make_float4(acc[h].x * inv, acc[h].y * inv, acc[h].z * inv, acc[h].w * inv);
    *reinterpret_cast<float4*>(&g_aggs[dst * 240 + h * 40 + 4 * gt]) = o;
  }
}

// ---------------- layer 3 prep ----------------
__global__ void l3_prep_v(const float* __restrict__ W3, const float* __restrict__ as3,
                          const float* __restrict__ ad3) {
  int t = threadIdx.x;
  if (t >= 240) return;
  int h = t / 40, k = t % 40;
  float s = 0.f, d = 0.f;
  for (int c = 0; c < 121; c++) {
    float w = W3[k * 726 + h * 121 + c];
    s += w * as3[h * 121 + c];
    d += w * ad3[h * 121 + c];
  }
  g_vsrc[t] = s;
  g_vdst[t] = d;
}

__global__ void l3_prep_w(const float* __restrict__ W3, const float* __restrict__ lw3,
                          const float* __restrict__ b3, const float* __restrict__ lb3) {
  int i = blockIdx.x * 256 + threadIdx.x;
  if (i < 280 * 128) {
    int r = i / 128, c = i % 128;
    float v = 0.f;
    if (c < 121)
      v = (r < 240) ? W3[(r % 40) * 726 + (r / 40) * 121 + c] * (1.f / 6.f)
                    : lw3[(r - 240) * 121 + c];
    g_wm[i] = v;
  }
  if (i < 128) g_biasc[i] = (i < 121) ? b3[i] + lb3[i] : 0.f;
}

__global__ __launch_bounds__(256) void l3_scores() {
  __shared__ float sVs[240], sVd[240];
  int t = threadIdx.x;
  if (t < 240) { sVs[t] = g_vsrc[t]; sVd[t] = g_vdst[t]; }
  __syncthreads();
  int n = blockIdx.x * 256 + t;
  if (n >= NN) return;
  float xr[40];
  const float4* hp = reinterpret_cast<const float4*>(&g_h[n * 40]);
#pragma unroll
  for (int j = 0; j < 10; j++) {
    float4 v = hp[j];
    xr[4 * j] = v.x; xr[4 * j + 1] = v.y; xr[4 * j + 2] = v.z; xr[4 * j + 3] = v.w;
  }
#pragma unroll
  for (int h = 0; h < 6; h++) {
    float s = 0.f, d = 0.f;
#pragma unroll
    for (int k = 0; k < 40; k++) { s += xr[k] * sVs[h * 40 + k]; d += xr[k] * sVd[h * 40 + k]; }
    g_asrc[n * 8 + h] = s;
    g_adst[n * 8 + h] = d;
  }
}

// ---------------- final fused GEMM: out = [aggs | h] @ Wm + biasc, f32x2 ----------------
// K tiled by 40 (280 = 7*40): each K-tile has a uniform source (aggs for kt<240,
// h for kt==240). All fills vectorized float4.
__global__ __launch_bounds__(256, 2) void final_gemm(float* __restrict__ out) {
  __shared__ __align__(16) float sA[40][128];
  __shared__ __align__(16) float sB[40][128];
  const int t = threadIdx.x;
  const int bm = blockIdx.x * 128;
  const int ty = t >> 4, tx = t & 15;
  const int fr = t >> 1;              // fill row 0..127
  const int fk = (t & 1) * 20;        // fill k-segment 0 or 20
  const bool valid = (bm + fr) < NN;
  u64 acc[8][4];
#pragma unroll
  for (int i = 0; i < 8; i++)
#pragma unroll
    for (int j = 0; j < 4; j++) acc[i][j] = 0ULL;

  for (int kt = 0; kt < 280; kt += 40) {
    // A fill: 128 rows x 40 k, each thread 5 float4 along k for one row
    {
      const int row = bm + fr;
      const float* srcA = (kt < 240) ? &g_aggs[(valid ? row : 0) * 240 + kt]
                                     : &g_h[(valid ? row : 0) * 40];
#pragma unroll
      for (int q = 0; q < 5; q++) {
        float4 v = valid ? *reinterpret_cast<const float4*>(srcA + fk + 4 * q)
                         : make_float4(0.f, 0.f, 0.f, 0.f);
        const int kk = fk + 4 * q;
        sA[kk][fr] = v.x;
        sA[kk + 1][fr] = v.y;
        sA[kk + 2][fr] = v.z;
        sA[kk + 3][fr] = v.w;
      }
    }
    // B fill: 40 x 128 floats = 1280 float4, 5 per thread, fully coalesced
#pragma unroll
    for (int q = 0; q < 5; q++) {
      const int idx = q * 256 + t;
      const int kk = idx >> 5, c4 = idx & 31;
      *reinterpret_cast<float4*>(&sB[kk][4 * c4]) =
          *reinterpret_cast<const float4*>(&g_wm[(kt + kk) * 128 + 4 * c4]);
    }
    __syncthreads();
#pragma unroll
    for (int kk = 0; kk < 40; kk++) {
      float a[8];
      u64 b[4];
#pragma unroll
      for (int i = 0; i < 8; i++) a[i] = sA[kk][ty * 8 + i];
      const u64* bp = reinterpret_cast<const u64*>(&sB[kk][tx * 8]);
#pragma unroll
      for (int j = 0; j < 4; j++) b[j] = bp[j];
#pragma unroll
      for (int i = 0; i < 8; i++) {
        u64 ap;
        asm("mov.b64 %0, {%1, %1};" : "=l"(ap) : "f"(a[i]));
#pragma unroll
        for (int j = 0; j < 4; j++)
          asm("fma.rn.f32x2 %0, %1, %2, %0;" : "+l"(acc[i][j]) : "l"(ap), "l"(b[j]));
      }
    }
    __syncthreads();
  }
#pragma unroll
  for (int i = 0; i < 8; i++) {
    int row = bm + ty * 8 + i;
    if (row >= NN) continue;
#pragma unroll
    for (int j = 0; j < 4; j++) {
      float lo, hi;
      asm("mov.b64 {%0, %1}, %2;" : "=f"(lo), "=f"(hi) : "l"(acc[i][j]));
      int c0 = tx * 8 + 2 * j;
      if (c0 < 121) out[row * 121 + c0] = lo + g_biasc[c0];
      if (c0 + 1 < 121) out[row * 121 + c0 + 1] = hi + g_biasc[c0 + 1];
    }
  }
}

// ---------------- launch ----------------
extern "C" void kernel_launch(void* const* d_in, const int* in_sizes, int n_in,
                              void* d_out, int out_size) {
  const float* x   = (const float*)d_in[0];
  const int*   ei  = (const int*)d_in[1];
  const float* W1  = (const float*)d_in[2];
  const float* as1 = (const float*)d_in[3];
  const float* ad1 = (const float*)d_in[4];
  const float* b1  = (const float*)d_in[5];
  const float* lw1 = (const float*)d_in[6];
  const float* lb1 = (const float*)d_in[7];
  const float* W2  = (const float*)d_in[8];
  const float* as2 = (const float*)d_in[9];
  const float* ad2 = (const float*)d_in[10];
  const float* b2  = (const float*)d_in[11];
  const float* lw2 = (const float*)d_in[12];
  const float* lb2 = (const float*)d_in[13];
  const float* W3  = (const float*)d_in[14];
  const float* as3 = (const float*)d_in[15];
  const float* ad3 = (const float*)d_in[16];
  const float* b3  = (const float*)d_in[17];
  const float* lw3 = (const float*)d_in[18];
  const float* lb3 = (const float*)d_in[19];
  float* out = (float*)d_out;

  float* hbuf = nullptr;
  cudaGetSymbolAddress((void**)&hbuf, g_h);

  const int EB = EE / 256;            // 6250 exact
  const int NB = (NN + 255) / 256;    // 391
  const int GB = (NN + 29) / 30;      // 3334 groups-of-30 blocks
  const int SB = (NN + 511) / 512;    // 196

  // CSR build (per launch; graph replays it deterministically)
  zero_deg<<<NB, 256>>>();
  hist_k<<<EB, 256>>>(ei);
  scan1_k<<<SB, 512>>>();
  scan2_k<<<1, 256>>>(SB);
  scan3_k<<<NB, 256>>>();
  scatter_k<<<EB, 256>>>(ei);

  // layer 1
  node_gemm_k<50><<<NN / 32, 128>>>(x, W1, lw1, lb1, as1, ad1);
  csr_agg_l12<<<GB, 320>>>(b1);
  // layer 2
  node_gemm_k<40><<<NN / 32, 128>>>(hbuf, W2, lw2, lb2, as2, ad2);
  csr_agg_l12<<<GB, 320>>>(b2);
  // layer 3
  l3_prep_v<<<1, 256>>>(W3, as3, ad3);
  l3_prep_w<<<140, 256>>>(W3, lw3, b3, lb3);
  l3_scores<<<NB, 256>>>();
  csr_agg_l3<<<GB, 320>>>();
  final_gemm<<<(NN + 127) / 128, 256>>>(out);
}